// round 5
// baseline (speedup 1.0000x reference)
#include <cuda_runtime.h>
#include <math.h>
#include <stdint.h>

// Problem constants
#define NG    4096
#define KPOS  4
#define H     256
#define MNEG  64
#define KDIM  768           // (KPOS-1)*H
#define LDA   1024          // hist_x[g] = emb[g*LDA .. g*LDA+KDIM)
#define NLOG  65

// Scratch
__device__ float g_pred[NG * H];    // split-K partial 0 (+bias)
__device__ float g_pred2[NG * H];   // split-K partial 1
__device__ float g_terms[NG];

// ---------------------------------------------------------------------------
// Kernel A: predicts = hist_x @ W + b  (M=4096, N=256, K=768), TF32 mma.sync
// BM=64 BN=64 BK=16. 256 threads = 8 warps: 2 k-groups x (2x2) warp grid,
// 32x32 warp tiles. Grid (4, 64, 2): z = outer split-K half (K=384 each),
// partials to g_pred / g_pred2 (summed in loss_kernel). 512 blocks total.
// cp.async 3-stage pipeline; RNA tf32 rounding applied in-register post-LDS.
// ---------------------------------------------------------------------------
#define BM 64
#define BN 64
#define BK 16
#define STAGES 3
#define KSPLIT 384                  // K per z-block
#define ITERS  (KSPLIT / BK)        // 24
#define A_STRIDE 20                 // BK + 4 pad (conflict-free frag LDS)
#define B_STRIDE 72                 // BN + 8 pad (conflict-free frag LDS)
#define A_STAGE_WORDS (BM * A_STRIDE)               // 1280
#define B_STAGE_WORDS (BK * B_STRIDE)               // 1152
#define STAGE_WORDS   (A_STAGE_WORDS + B_STAGE_WORDS)  // 2432

__device__ __forceinline__ void cp16(float* dst_smem, const float* src) {
    uint32_t d = (uint32_t)__cvta_generic_to_shared(dst_smem);
    asm volatile("cp.async.cg.shared.global [%0], [%1], 16;\n" :: "r"(d), "l"(src));
}

__device__ __forceinline__ uint32_t ld_tf32(const float* p) {
    uint32_t u;
    asm("cvt.rna.tf32.f32 %0, %1;" : "=r"(u) : "f"(*p));
    return u;
}

__global__ __launch_bounds__(256) void gemm_tc(const float* __restrict__ A,
                                               const float* __restrict__ W,
                                               const float* __restrict__ bias) {
    __shared__ __align__(16) float smem[STAGES * STAGE_WORDS];

    const int tid  = threadIdx.x;
    const int warp = tid >> 5;
    const int lane = tid & 31;
    const int kg   = warp >> 2;          // k-group: 0 or 1
    const int wq   = warp & 3;           // warp position in 2x2
    const int wm0  = (wq >> 1) * 32;
    const int wn0  = (wq & 1) * 32;
    const int bm0  = blockIdx.y * BM;
    const int bn0  = blockIdx.x * BN;
    const int kz   = blockIdx.z * KSPLIT;

    const int mrow = lane >> 2;          // mma groupID
    const int kq   = lane & 3;           // mma threadID-in-group
    const int kb   = kg * 8;             // warp's k-offset within BK tile

    // cp.async mappings
    const int am  = tid >> 2;            // A row 0..63
    const int ak4 = (tid & 3) * 4;       // A k offset {0,4,8,12}
    const int bkr = tid >> 4;            // B k row 0..15
    const int bn4 = (tid & 15) * 4;      // B n offset

    const float* Abase = A + (size_t)(bm0 + am) * LDA + kz + ak4;
    const float* Wbase = W + (size_t)(kz + bkr) * H + bn0 + bn4;

    float c[2][4][4];
#pragma unroll
    for (int i = 0; i < 2; i++)
#pragma unroll
        for (int j = 0; j < 4; j++)
#pragma unroll
            for (int q = 0; q < 4; q++) c[i][j][q] = 0.0f;

    // prologue: preload stages 0..1
#pragma unroll
    for (int s = 0; s < STAGES - 1; s++) {
        float* st = smem + s * STAGE_WORDS;
        cp16(st + am * A_STRIDE + ak4, Abase + s * BK);
        cp16(st + A_STAGE_WORDS + bkr * B_STRIDE + bn4, Wbase + (size_t)s * BK * H);
        asm volatile("cp.async.commit_group;\n" ::: "memory");
    }

#pragma unroll 3
    for (int it = 0; it < ITERS; it++) {
        asm volatile("cp.async.wait_group 1;\n" ::: "memory");
        __syncthreads();

        int nit = it + STAGES - 1;
        if (nit < ITERS) {
            float* st = smem + (nit % STAGES) * STAGE_WORDS;
            cp16(st + am * A_STRIDE + ak4, Abase + nit * BK);
            cp16(st + A_STAGE_WORDS + bkr * B_STRIDE + bn4,
                 Wbase + (size_t)nit * BK * H);
        }
        asm volatile("cp.async.commit_group;\n" ::: "memory");

        const float* As = smem + (it % STAGES) * STAGE_WORDS;
        const float* Bs = As + A_STAGE_WORDS;

        uint32_t a[2][4], b[4][2];
#pragma unroll
        for (int mf = 0; mf < 2; mf++) {
            int m = wm0 + mf * 16 + mrow;
            a[mf][0] = ld_tf32(&As[m * A_STRIDE + kb + kq]);
            a[mf][1] = ld_tf32(&As[(m + 8) * A_STRIDE + kb + kq]);
            a[mf][2] = ld_tf32(&As[m * A_STRIDE + kb + kq + 4]);
            a[mf][3] = ld_tf32(&As[(m + 8) * A_STRIDE + kb + kq + 4]);
        }
#pragma unroll
        for (int nf = 0; nf < 4; nf++) {
            int n = wn0 + nf * 8 + mrow;
            b[nf][0] = ld_tf32(&Bs[(kb + kq) * B_STRIDE + n]);
            b[nf][1] = ld_tf32(&Bs[(kb + kq + 4) * B_STRIDE + n]);
        }
#pragma unroll
        for (int mf = 0; mf < 2; mf++)
#pragma unroll
            for (int nf = 0; nf < 4; nf++) {
                asm volatile(
                    "mma.sync.aligned.m16n8k8.row.col.f32.tf32.tf32.f32 "
                    "{%0,%1,%2,%3}, {%4,%5,%6,%7}, {%8,%9}, {%0,%1,%2,%3};"
                    : "+f"(c[mf][nf][0]), "+f"(c[mf][nf][1]),
                      "+f"(c[mf][nf][2]), "+f"(c[mf][nf][3])
                    : "r"(a[mf][0]), "r"(a[mf][1]), "r"(a[mf][2]), "r"(a[mf][3]),
                      "r"(b[nf][0]), "r"(b[nf][1]));
            }
    }

    // epilogue: cross-kgroup reduction through smem, (+bias for z=0), store
    __syncthreads();
    if (kg == 1) {
        float* red = smem + wq * 1024;
        int i = 0;
#pragma unroll
        for (int mf = 0; mf < 2; mf++)
#pragma unroll
            for (int nf = 0; nf < 4; nf++)
#pragma unroll
                for (int q = 0; q < 4; q++) {
                    red[i * 32 + lane] = c[mf][nf][q];
                    i++;
                }
    }
    __syncthreads();
    if (kg == 0) {
        const float* red = smem + wq * 1024;
        int i = 0;
#pragma unroll
        for (int mf = 0; mf < 2; mf++)
#pragma unroll
            for (int nf = 0; nf < 4; nf++)
#pragma unroll
                for (int q = 0; q < 4; q++) {
                    c[mf][nf][q] += red[i * 32 + lane];
                    i++;
                }
        float* outb = (blockIdx.z == 0) ? g_pred : g_pred2;
#pragma unroll
        for (int mf = 0; mf < 2; mf++) {
            int m = bm0 + wm0 + mf * 16 + mrow;
#pragma unroll
            for (int nf = 0; nf < 4; nf++) {
                int n = bn0 + wn0 + nf * 8 + kq * 2;
                float bx = 0.0f, by = 0.0f;
                if (blockIdx.z == 0) {
                    float2 bb = *(const float2*)(bias + n);
                    bx = bb.x; by = bb.y;
                }
                float2 o0 = make_float2(c[mf][nf][0] + bx, c[mf][nf][1] + by);
                float2 o1 = make_float2(c[mf][nf][2] + bx, c[mf][nf][3] + by);
                *(float2*)&outb[(size_t)m * H + n] = o0;
                *(float2*)&outb[(size_t)(m + 8) * H + n] = o1;
            }
        }
    }
}

// ---------------------------------------------------------------------------
// Kernel B: per-group logits + log-softmax term (L2-gather bound).
// Sums the two split-K partials while staging s_pred.
// ---------------------------------------------------------------------------
__global__ __launch_bounds__(256) void loss_kernel(const float* __restrict__ emb,
                                                   const int* __restrict__ perm) {
    const int g    = blockIdx.x;
    const int tid  = threadIdx.x;
    const int warp = tid >> 5;
    const int lane = tid & 31;

    __shared__ float s_pred[H];
    __shared__ float s_logits[NLOG];
    __shared__ int   s_row[NLOG];

    s_pred[tid] = g_pred[(size_t)g * H + tid] + g_pred2[(size_t)g * H + tid];
    if (tid < MNEG) {
        int p = perm[(size_t)g * MNEG + tid];
        s_row[tid + 1] = p + ((p >= 4 * g) ? 4 : 0);
    }
    if (tid == MNEG) s_row[0] = 4 * g + 3;
    __syncthreads();

    const float4* p4 = (const float4*)s_pred;
    const float4 pa = p4[lane];
    const float4 pb = p4[lane + 32];

    for (int j = warp; j < NLOG; j += 8) {
        const float4* e4 = (const float4*)(emb + (size_t)s_row[j] * H);
        float4 ea = e4[lane];
        float4 eb = e4[lane + 32];
        float s = ea.x * pa.x + ea.y * pa.y + ea.z * pa.z + ea.w * pa.w
                + eb.x * pb.x + eb.y * pb.y + eb.z * pb.z + eb.w * pb.w;
#pragma unroll
        for (int off = 16; off > 0; off >>= 1)
            s += __shfl_down_sync(0xffffffffu, s, off);
        if (lane == 0) s_logits[j] = s;
    }
    __syncthreads();

    if (warp == 0) {
        float v0 = s_logits[lane];
        float v1 = s_logits[lane + 32];
        float v2 = (lane == 0) ? s_logits[64] : -INFINITY;
        float m = fmaxf(fmaxf(v0, v1), v2);
#pragma unroll
        for (int off = 16; off > 0; off >>= 1)
            m = fmaxf(m, __shfl_xor_sync(0xffffffffu, m, off));
        float s = expf(v0 - m) + expf(v1 - m) + ((lane == 0) ? expf(v2 - m) : 0.0f);
#pragma unroll
        for (int off = 16; off > 0; off >>= 1)
            s += __shfl_xor_sync(0xffffffffu, s, off);
        float lse = m + logf(s);
        if (lane == 0) g_terms[g] = lse - s_logits[0];
    }
}

// ---------------------------------------------------------------------------
// Kernel C: deterministic mean
// ---------------------------------------------------------------------------
__global__ __launch_bounds__(256) void reduce_kernel(float* __restrict__ out) {
    __shared__ float s[256];
    float v = 0.0f;
    for (int i = threadIdx.x; i < NG; i += 256)
        v += g_terms[i];
    s[threadIdx.x] = v;
    __syncthreads();
    for (int st = 128; st > 0; st >>= 1) {
        if (threadIdx.x < st) s[threadIdx.x] += s[threadIdx.x + st];
        __syncthreads();
    }
    if (threadIdx.x == 0) out[0] = s[0] / (float)NG;
}

// ---------------------------------------------------------------------------
extern "C" void kernel_launch(void* const* d_in, const int* in_sizes, int n_in,
                              void* d_out, int out_size) {
    const float* emb  = (const float*)d_in[0];   // (16384, 256) f32
    const float* W    = (const float*)d_in[1];   // (768, 256)   f32
    const float* bias = (const float*)d_in[2];   // (256,)       f32
    // d_in[3] = target (analytic, unused)
    const int* perm   = (const int*)d_in[4];     // (4096, 64)   int32

    dim3 ggrid(H / BN, NG / BM, 2);   // (4, 64, 2) = 512 blocks
    gemm_tc<<<ggrid, 256>>>(emb, W, bias);
    loss_kernel<<<NG, 256>>>(emb, perm);
    reduce_kernel<<<1, 256>>>((float*)d_out);
}

// round 6
// speedup vs baseline: 1.0347x; 1.0347x over previous
#include <cuda_runtime.h>
#include <cuda_bf16.h>
#include <math.h>
#include <stdint.h>

// Problem constants
#define NG    4096
#define KPOS  4
#define H     256
#define MNEG  64
#define KDIM  768           // (KPOS-1)*H
#define LDA   1024          // hist_x[g] = emb[g*LDA .. g*LDA+KDIM)
#define NLOG  65

#define ZSPLIT 4
#define KS    (KDIM / ZSPLIT)   // 192 k per z-block

// Scratch (static device arrays; allocation-free rule)
__device__ __nv_bfloat16 g_Abf[NG * KDIM];      // emb-hist, bf16, packed lda=768
__device__ __nv_bfloat16 g_WTbf[H * KDIM];      // W^T, bf16, [n][k]
__device__ float g_pred4[ZSPLIT * NG * H];      // split-K partials (z=0 carries bias)
__device__ float g_terms[NG];

// ---------------------------------------------------------------------------
// Kernel 0: convert emb-hist -> bf16 packed, W -> bf16 transposed.
// ---------------------------------------------------------------------------
#define EMB_PAIRS (NG * KDIM / 2)        // 1,572,864 bf162 pairs
#define EMB_BLOCKS (EMB_PAIRS / 256)     // 6144
#define WT_BLOCKS  (H * KDIM / 256)      // 768

__global__ __launch_bounds__(256) void convert_kernel(const float* __restrict__ emb,
                                                      const float* __restrict__ W) {
    int b = blockIdx.x;
    if (b < EMB_BLOCKS) {
        int idx = b * 256 + threadIdx.x;          // pair index
        int g = idx / (KDIM / 2);
        int j = idx % (KDIM / 2);
        float2 v = *(const float2*)(emb + (size_t)g * LDA + 2 * j);
        *(__nv_bfloat162*)&g_Abf[(size_t)g * KDIM + 2 * j] =
            __floats2bfloat162_rn(v.x, v.y);
    } else {
        int t = (b - EMB_BLOCKS) * 256 + threadIdx.x;   // 0 .. H*KDIM-1
        int n = t / KDIM;
        int k = t % KDIM;
        g_WTbf[t] = __float2bfloat16_rn(W[(size_t)k * H + n]);  // write coalesced
    }
}

// ---------------------------------------------------------------------------
// Kernel A: predicts = hist_x @ W + b  via bf16 mma.m16n8k16, fp32 accum.
// BM=64 BN=64 BK=16, 128 threads = 4 warps (2x2), warp tile 32x32.
// Grid (4, 64, 4): z = split-K quarter (K=192 each) into g_pred4.
// 4-stage cp.async pipeline; zero conversions in the mainloop.
// ---------------------------------------------------------------------------
#define BKH 16                       // k (halves) per iteration
#define ITERS (KS / BKH)             // 12
#define STG 4
#define ROWH 24                      // padded halves per smem row (conflict-free)
#define A_ST_H (64 * ROWH)           // 1536 halves
#define STAGE_H (2 * A_ST_H)         // 3072 halves = 6144 B; x4 stages = 24.6 KB

__device__ __forceinline__ void cp16b(__nv_bfloat16* dst_smem, const __nv_bfloat16* src) {
    uint32_t d = (uint32_t)__cvta_generic_to_shared(dst_smem);
    asm volatile("cp.async.cg.shared.global [%0], [%1], 16;\n" :: "r"(d), "l"(src));
}

__global__ __launch_bounds__(128) void gemm_bf16(const float* __restrict__ bias) {
    __shared__ __align__(16) __nv_bfloat16 smem[STG * STAGE_H];

    const int tid  = threadIdx.x;
    const int warp = tid >> 5;
    const int lane = tid & 31;
    const int gid  = lane >> 2;          // mma groupID (row within 8)
    const int tq   = lane & 3;           // mma threadID-in-group
    const int wm0  = (warp >> 1) * 32;
    const int wn0  = (warp & 1) * 32;
    const int bm0  = blockIdx.y * 64;
    const int bn0  = blockIdx.x * 64;
    const int kz   = blockIdx.z * KS;

    // cp.async mapping: thread -> (row, 8-half chunk); covers A rows + B rows
    const int crow = tid >> 1;           // 0..63
    const int koff = (tid & 1) * 8;      // halves

    const __nv_bfloat16* Asrc = g_Abf  + (size_t)(bm0 + crow) * KDIM + kz + koff;
    const __nv_bfloat16* Bsrc = g_WTbf + (size_t)(bn0 + crow) * KDIM + kz + koff;

    float c[2][4][4];
#pragma unroll
    for (int i = 0; i < 2; i++)
#pragma unroll
        for (int j = 0; j < 4; j++)
#pragma unroll
            for (int q = 0; q < 4; q++) c[i][j][q] = 0.0f;

    // prologue: stages 0..2
#pragma unroll
    for (int s = 0; s < STG - 1; s++) {
        __nv_bfloat16* st = smem + s * STAGE_H;
        cp16b(st + crow * ROWH + koff, Asrc + s * BKH);
        cp16b(st + A_ST_H + crow * ROWH + koff, Bsrc + s * BKH);
        asm volatile("cp.async.commit_group;\n" ::: "memory");
    }

#pragma unroll 4
    for (int it = 0; it < ITERS; it++) {
        asm volatile("cp.async.wait_group 2;\n" ::: "memory");
        __syncthreads();

        int nit = it + STG - 1;
        if (nit < ITERS) {
            __nv_bfloat16* st = smem + (nit % STG) * STAGE_H;
            cp16b(st + crow * ROWH + koff, Asrc + nit * BKH);
            cp16b(st + A_ST_H + crow * ROWH + koff, Bsrc + nit * BKH);
        }
        asm volatile("cp.async.commit_group;\n" ::: "memory");

        const __nv_bfloat16* As = smem + (it % STG) * STAGE_H;
        const __nv_bfloat16* Bs = As + A_ST_H;

        uint32_t a[2][4], b[4][2];
#pragma unroll
        for (int mf = 0; mf < 2; mf++) {
            int m = wm0 + mf * 16 + gid;
            a[mf][0] = *(const uint32_t*)&As[m * ROWH + 2 * tq];
            a[mf][1] = *(const uint32_t*)&As[(m + 8) * ROWH + 2 * tq];
            a[mf][2] = *(const uint32_t*)&As[m * ROWH + 2 * tq + 8];
            a[mf][3] = *(const uint32_t*)&As[(m + 8) * ROWH + 2 * tq + 8];
        }
#pragma unroll
        for (int nf = 0; nf < 4; nf++) {
            int n = wn0 + nf * 8 + gid;
            b[nf][0] = *(const uint32_t*)&Bs[n * ROWH + 2 * tq];
            b[nf][1] = *(const uint32_t*)&Bs[n * ROWH + 2 * tq + 8];
        }
#pragma unroll
        for (int mf = 0; mf < 2; mf++)
#pragma unroll
            for (int nf = 0; nf < 4; nf++) {
                asm volatile(
                    "mma.sync.aligned.m16n8k16.row.col.f32.bf16.bf16.f32 "
                    "{%0,%1,%2,%3}, {%4,%5,%6,%7}, {%8,%9}, {%0,%1,%2,%3};"
                    : "+f"(c[mf][nf][0]), "+f"(c[mf][nf][1]),
                      "+f"(c[mf][nf][2]), "+f"(c[mf][nf][3])
                    : "r"(a[mf][0]), "r"(a[mf][1]), "r"(a[mf][2]), "r"(a[mf][3]),
                      "r"(b[nf][0]), "r"(b[nf][1]));
            }
    }

    // epilogue: direct store of warp-owned 32x32 tile into partial z buffer
    float* outb = g_pred4 + (size_t)blockIdx.z * NG * H;
#pragma unroll
    for (int mf = 0; mf < 2; mf++) {
        int m = bm0 + wm0 + mf * 16 + gid;
#pragma unroll
        for (int nf = 0; nf < 4; nf++) {
            int n = bn0 + wn0 + nf * 8 + 2 * tq;
            float bx = 0.0f, by = 0.0f;
            if (blockIdx.z == 0) {
                float2 bb = *(const float2*)(bias + n);
                bx = bb.x; by = bb.y;
            }
            *(float2*)&outb[(size_t)m * H + n] =
                make_float2(c[mf][nf][0] + bx, c[mf][nf][1] + by);
            *(float2*)&outb[(size_t)(m + 8) * H + n] =
                make_float2(c[mf][nf][2] + bx, c[mf][nf][3] + by);
        }
    }
}

// ---------------------------------------------------------------------------
// Kernel B: per-group logits + log-softmax term (L2-gather bound).
// Sums the 4 split-K partials while staging s_pred.
// ---------------------------------------------------------------------------
__global__ __launch_bounds__(256) void loss_kernel(const float* __restrict__ emb,
                                                   const int* __restrict__ perm) {
    const int g    = blockIdx.x;
    const int tid  = threadIdx.x;
    const int warp = tid >> 5;
    const int lane = tid & 31;

    __shared__ float s_pred[H];
    __shared__ float s_logits[NLOG];
    __shared__ int   s_row[NLOG];

    {
        const float* pp = g_pred4 + (size_t)g * H + tid;
        s_pred[tid] = (pp[0] + pp[(size_t)NG * H])
                    + (pp[2 * (size_t)NG * H] + pp[3 * (size_t)NG * H]);
    }
    if (tid < MNEG) {
        int p = perm[(size_t)g * MNEG + tid];
        s_row[tid + 1] = p + ((p >= 4 * g) ? 4 : 0);
    }
    if (tid == MNEG) s_row[0] = 4 * g + 3;
    __syncthreads();

    const float4* p4 = (const float4*)s_pred;
    const float4 pa = p4[lane];
    const float4 pb = p4[lane + 32];

    for (int j = warp; j < NLOG; j += 8) {
        const float4* e4 = (const float4*)(emb + (size_t)s_row[j] * H);
        float4 ea = e4[lane];
        float4 eb = e4[lane + 32];
        float s = ea.x * pa.x + ea.y * pa.y + ea.z * pa.z + ea.w * pa.w
                + eb.x * pb.x + eb.y * pb.y + eb.z * pb.z + eb.w * pb.w;
#pragma unroll
        for (int off = 16; off > 0; off >>= 1)
            s += __shfl_down_sync(0xffffffffu, s, off);
        if (lane == 0) s_logits[j] = s;
    }
    __syncthreads();

    if (warp == 0) {
        float v0 = s_logits[lane];
        float v1 = s_logits[lane + 32];
        float v2 = (lane == 0) ? s_logits[64] : -INFINITY;
        float m = fmaxf(fmaxf(v0, v1), v2);
#pragma unroll
        for (int off = 16; off > 0; off >>= 1)
            m = fmaxf(m, __shfl_xor_sync(0xffffffffu, m, off));
        float s = expf(v0 - m) + expf(v1 - m) + ((lane == 0) ? expf(v2 - m) : 0.0f);
#pragma unroll
        for (int off = 16; off > 0; off >>= 1)
            s += __shfl_xor_sync(0xffffffffu, s, off);
        float lse = m + logf(s);
        if (lane == 0) g_terms[g] = lse - s_logits[0];
    }
}

// ---------------------------------------------------------------------------
// Kernel C: deterministic mean
// ---------------------------------------------------------------------------
__global__ __launch_bounds__(256) void reduce_kernel(float* __restrict__ out) {
    __shared__ float s[256];
    float v = 0.0f;
    for (int i = threadIdx.x; i < NG; i += 256)
        v += g_terms[i];
    s[threadIdx.x] = v;
    __syncthreads();
    for (int st = 128; st > 0; st >>= 1) {
        if (threadIdx.x < st) s[threadIdx.x] += s[threadIdx.x + st];
        __syncthreads();
    }
    if (threadIdx.x == 0) out[0] = s[0] / (float)NG;
}

// ---------------------------------------------------------------------------
extern "C" void kernel_launch(void* const* d_in, const int* in_sizes, int n_in,
                              void* d_out, int out_size) {
    const float* emb  = (const float*)d_in[0];   // (16384, 256) f32
    const float* W    = (const float*)d_in[1];   // (768, 256)   f32
    const float* bias = (const float*)d_in[2];   // (256,)       f32
    // d_in[3] = target (analytic, unused)
    const int* perm   = (const int*)d_in[4];     // (4096, 64)   int32

    convert_kernel<<<EMB_BLOCKS + WT_BLOCKS, 256>>>(emb, W);
    dim3 ggrid(H / 64, NG / 64, ZSPLIT);   // (4, 64, 4) = 1024 blocks
    gemm_bf16<<<ggrid, 128>>>(bias);
    loss_kernel<<<NG, 256>>>(emb, perm);
    reduce_kernel<<<1, 256>>>((float*)d_out);
}

// round 7
// speedup vs baseline: 1.1590x; 1.1201x over previous
#include <cuda_runtime.h>
#include <cuda_bf16.h>
#include <math.h>
#include <stdint.h>

// Problem constants
#define NG    4096
#define KPOS  4
#define H     256
#define MNEG  64
#define NROWS (NG * KPOS)       // 16384 embedding rows
#define KDIM  768               // (KPOS-1)*H
#define LDAH  1024              // halves per emb row-group in g_Ebf (KPOS*H)
#define NLOG  65

#define ZSPLIT 4
#define KS    (KDIM / ZSPLIT)   // 192 k per z-block

// Scratch (static device arrays; allocation-free rule)
__device__ __align__(16) __nv_bfloat16 g_Ebf[NROWS * H];   // full emb, bf16 (8 MB)
__device__ __align__(16) __nv_bfloat16 g_WTbf[H * KDIM];   // W^T, bf16, [n][k]
__device__ float g_pred4[ZSPLIT * NG * H];                 // split-K partials
__device__ float g_terms[NG];

// ---------------------------------------------------------------------------
// Kernel 0: convert full emb -> bf16, W -> bf16 transposed.
// ---------------------------------------------------------------------------
#define EMB_PAIRS  (NROWS * H / 2)        // 2,097,152
#define EMB_BLOCKS (EMB_PAIRS / 256)      // 8192
#define WT_BLOCKS  (H * KDIM / 256)       // 768

__global__ __launch_bounds__(256) void convert_kernel(const float* __restrict__ emb,
                                                      const float* __restrict__ W) {
    int b = blockIdx.x;
    if (b < EMB_BLOCKS) {
        int idx = b * 256 + threadIdx.x;          // pair index
        float2 v = *(const float2*)(emb + 2 * (size_t)idx);
        *(__nv_bfloat162*)&g_Ebf[2 * (size_t)idx] = __floats2bfloat162_rn(v.x, v.y);
    } else {
        int t = (b - EMB_BLOCKS) * 256 + threadIdx.x;   // 0 .. H*KDIM-1
        int n = t / KDIM;
        int k = t % KDIM;
        g_WTbf[t] = __float2bfloat16_rn(W[(size_t)k * H + n]);  // coalesced write
    }
}

// ---------------------------------------------------------------------------
// Kernel A: predicts = hist_x @ W + b  via bf16 mma.m16n8k16, fp32 accum.
// A read from g_Ebf with lda=1024 halves (hist view = emb rows in place).
// BM=64 BN=64 BK=16, 128 threads = 4 warps (2x2), warp tile 32x32.
// Grid (4, 64, 4): z = split-K quarter (K=192 each) into g_pred4.
// ---------------------------------------------------------------------------
#define BKH 16                       // k halves per iteration
#define ITERS (KS / BKH)             // 12
#define STG 4
#define ROWH 24                      // padded halves per smem row (conflict-free)
#define A_ST_H (64 * ROWH)           // 1536 halves
#define STAGE_H (2 * A_ST_H)         // 3072 halves = 6144 B

__device__ __forceinline__ void cp16b(__nv_bfloat16* dst_smem, const __nv_bfloat16* src) {
    uint32_t d = (uint32_t)__cvta_generic_to_shared(dst_smem);
    asm volatile("cp.async.cg.shared.global [%0], [%1], 16;\n" :: "r"(d), "l"(src));
}

__global__ __launch_bounds__(128) void gemm_bf16(const float* __restrict__ bias) {
    __shared__ __align__(16) __nv_bfloat16 smem[STG * STAGE_H];

    const int tid  = threadIdx.x;
    const int warp = tid >> 5;
    const int lane = tid & 31;
    const int gid  = lane >> 2;          // mma groupID
    const int tq   = lane & 3;           // mma threadID-in-group
    const int wm0  = (warp >> 1) * 32;
    const int wn0  = (warp & 1) * 32;
    const int bm0  = blockIdx.y * 64;
    const int bn0  = blockIdx.x * 64;
    const int kz   = blockIdx.z * KS;

    const int crow = tid >> 1;           // 0..63
    const int koff = (tid & 1) * 8;      // halves

    const __nv_bfloat16* Asrc = g_Ebf  + (size_t)(bm0 + crow) * LDAH + kz + koff;
    const __nv_bfloat16* Bsrc = g_WTbf + (size_t)(bn0 + crow) * KDIM + kz + koff;

    float c[2][4][4];
#pragma unroll
    for (int i = 0; i < 2; i++)
#pragma unroll
        for (int j = 0; j < 4; j++)
#pragma unroll
            for (int q = 0; q < 4; q++) c[i][j][q] = 0.0f;

#pragma unroll
    for (int s = 0; s < STG - 1; s++) {
        __nv_bfloat16* st = smem + s * STAGE_H;
        cp16b(st + crow * ROWH + koff, Asrc + s * BKH);
        cp16b(st + A_ST_H + crow * ROWH + koff, Bsrc + s * BKH);
        asm volatile("cp.async.commit_group;\n" ::: "memory");
    }

#pragma unroll 4
    for (int it = 0; it < ITERS; it++) {
        asm volatile("cp.async.wait_group 2;\n" ::: "memory");
        __syncthreads();

        int nit = it + STG - 1;
        if (nit < ITERS) {
            __nv_bfloat16* st = smem + (nit % STG) * STAGE_H;
            cp16b(st + crow * ROWH + koff, Asrc + nit * BKH);
            cp16b(st + A_ST_H + crow * ROWH + koff, Bsrc + nit * BKH);
        }
        asm volatile("cp.async.commit_group;\n" ::: "memory");

        const __nv_bfloat16* As = smem + (it % STG) * STAGE_H;
        const __nv_bfloat16* Bs = As + A_ST_H;

        uint32_t a[2][4], b[4][2];
#pragma unroll
        for (int mf = 0; mf < 2; mf++) {
            int m = wm0 + mf * 16 + gid;
            a[mf][0] = *(const uint32_t*)&As[m * ROWH + 2 * tq];
            a[mf][1] = *(const uint32_t*)&As[(m + 8) * ROWH + 2 * tq];
            a[mf][2] = *(const uint32_t*)&As[m * ROWH + 2 * tq + 8];
            a[mf][3] = *(const uint32_t*)&As[(m + 8) * ROWH + 2 * tq + 8];
        }
#pragma unroll
        for (int nf = 0; nf < 4; nf++) {
            int n = wn0 + nf * 8 + gid;
            b[nf][0] = *(const uint32_t*)&Bs[n * ROWH + 2 * tq];
            b[nf][1] = *(const uint32_t*)&Bs[n * ROWH + 2 * tq + 8];
        }
#pragma unroll
        for (int mf = 0; mf < 2; mf++)
#pragma unroll
            for (int nf = 0; nf < 4; nf++) {
                asm volatile(
                    "mma.sync.aligned.m16n8k16.row.col.f32.bf16.bf16.f32 "
                    "{%0,%1,%2,%3}, {%4,%5,%6,%7}, {%8,%9}, {%0,%1,%2,%3};"
                    : "+f"(c[mf][nf][0]), "+f"(c[mf][nf][1]),
                      "+f"(c[mf][nf][2]), "+f"(c[mf][nf][3])
                    : "r"(a[mf][0]), "r"(a[mf][1]), "r"(a[mf][2]), "r"(a[mf][3]),
                      "r"(b[nf][0]), "r"(b[nf][1]));
            }
    }

    float* outb = g_pred4 + (size_t)blockIdx.z * NG * H;
#pragma unroll
    for (int mf = 0; mf < 2; mf++) {
        int m = bm0 + wm0 + mf * 16 + gid;
#pragma unroll
        for (int nf = 0; nf < 4; nf++) {
            int n = bn0 + wn0 + nf * 8 + 2 * tq;
            float bx = 0.0f, by = 0.0f;
            if (blockIdx.z == 0) {
                float2 bb = *(const float2*)(bias + n);
                bx = bb.x; by = bb.y;
            }
            *(float2*)&outb[(size_t)m * H + n] =
                make_float2(c[mf][nf][0] + bx, c[mf][nf][1] + by);
            *(float2*)&outb[(size_t)(m + 8) * H + n] =
                make_float2(c[mf][nf][2] + bx, c[mf][nf][3] + by);
        }
    }
}

// ---------------------------------------------------------------------------
// Kernel B: per-group logits + log-softmax term.
// bf16 gather (512 B/row, one uint4 per lane), fp32 dot with s_pred.
// ---------------------------------------------------------------------------
__global__ __launch_bounds__(256) void loss_kernel(const int* __restrict__ perm) {
    const int g    = blockIdx.x;
    const int tid  = threadIdx.x;
    const int warp = tid >> 5;
    const int lane = tid & 31;

    __shared__ float s_pred[H];
    __shared__ float s_logits[NLOG];
    __shared__ int   s_row[NLOG];

    {
        const float* pp = g_pred4 + (size_t)g * H + tid;
        s_pred[tid] = (pp[0] + pp[(size_t)NG * H])
                    + (pp[2 * (size_t)NG * H] + pp[3 * (size_t)NG * H]);
    }
    if (tid < MNEG) {
        int p = perm[(size_t)g * MNEG + tid];
        s_row[tid + 1] = p + ((p >= 4 * g) ? 4 : 0);
    }
    if (tid == MNEG) s_row[0] = 4 * g + 3;
    __syncthreads();

    // each lane owns 8 consecutive pred floats (halves 8*lane .. 8*lane+7)
    const float4* p4 = (const float4*)s_pred;
    const float4 pa = p4[2 * lane];
    const float4 pb = p4[2 * lane + 1];

    for (int j = warp; j < NLOG; j += 8) {
        const uint4* e = (const uint4*)(g_Ebf + (size_t)s_row[j] * H);
        uint4 v = e[lane];                       // 8 bf16 halves
        float2 f0 = __bfloat1622float2(*(const __nv_bfloat162*)&v.x);
        float2 f1 = __bfloat1622float2(*(const __nv_bfloat162*)&v.y);
        float2 f2 = __bfloat1622float2(*(const __nv_bfloat162*)&v.z);
        float2 f3 = __bfloat1622float2(*(const __nv_bfloat162*)&v.w);
        float s = f0.x * pa.x + f0.y * pa.y + f1.x * pa.z + f1.y * pa.w
                + f2.x * pb.x + f2.y * pb.y + f3.x * pb.z + f3.y * pb.w;
#pragma unroll
        for (int off = 16; off > 0; off >>= 1)
            s += __shfl_down_sync(0xffffffffu, s, off);
        if (lane == 0) s_logits[j] = s;
    }
    __syncthreads();

    if (warp == 0) {
        float v0 = s_logits[lane];
        float v1 = s_logits[lane + 32];
        float v2 = (lane == 0) ? s_logits[64] : -INFINITY;
        float m = fmaxf(fmaxf(v0, v1), v2);
#pragma unroll
        for (int off = 16; off > 0; off >>= 1)
            m = fmaxf(m, __shfl_xor_sync(0xffffffffu, m, off));
        float s = expf(v0 - m) + expf(v1 - m) + ((lane == 0) ? expf(v2 - m) : 0.0f);
#pragma unroll
        for (int off = 16; off > 0; off >>= 1)
            s += __shfl_xor_sync(0xffffffffu, s, off);
        float lse = m + logf(s);
        if (lane == 0) g_terms[g] = lse - s_logits[0];
    }
}

// ---------------------------------------------------------------------------
// Kernel C: deterministic mean. 256 thr, 16 contiguous floats each (4x float4).
// ---------------------------------------------------------------------------
__global__ __launch_bounds__(256) void reduce_kernel(float* __restrict__ out) {
    __shared__ float s[256];
    const int t = threadIdx.x;
    const float4* p = (const float4*)g_terms;
    float4 a = p[4 * t + 0];
    float4 b = p[4 * t + 1];
    float4 c = p[4 * t + 2];
    float4 d = p[4 * t + 3];
    float v = ((a.x + a.y) + (a.z + a.w)) + ((b.x + b.y) + (b.z + b.w))
            + ((c.x + c.y) + (c.z + c.w)) + ((d.x + d.y) + (d.z + d.w));
    s[t] = v;
    __syncthreads();
    for (int st = 128; st > 0; st >>= 1) {
        if (t < st) s[t] += s[t + st];
        __syncthreads();
    }
    if (t == 0) out[0] = s[0] / (float)NG;
}

// ---------------------------------------------------------------------------
extern "C" void kernel_launch(void* const* d_in, const int* in_sizes, int n_in,
                              void* d_out, int out_size) {
    const float* emb  = (const float*)d_in[0];   // (16384, 256) f32
    const float* W    = (const float*)d_in[1];   // (768, 256)   f32
    const float* bias = (const float*)d_in[2];   // (256,)       f32
    // d_in[3] = target (analytic, unused)
    const int* perm   = (const int*)d_in[4];     // (4096, 64)   int32

    convert_kernel<<<EMB_BLOCKS + WT_BLOCKS, 256>>>(emb, W);
    dim3 ggrid(H / 64, NG / 64, ZSPLIT);   // (4, 64, 4) = 1024 blocks
    gemm_bf16<<<ggrid, 128>>>(bias);
    loss_kernel<<<NG, 256>>>(perm);
    reduce_kernel<<<1, 256>>>((float*)d_out);
}